// round 4
// baseline (speedup 1.0000x reference)
#include <cuda_runtime.h>
#include <math.h>

// Problem constants (PerturbationAttention): delta [B, C, D] fp32, k = 256
#define B_DIM 2048
#define C_DIM 512
#define D_DIM 256
#define K_SEL 256
#define SIG_BLOCKS 296   // 148 SMs * 2 resident blocks of 512 threads

// Scratch (no allocations allowed): sigma buffer (4 MB) + per-block maxima.
__device__ float g_sigma[B_DIM * C_DIM];
__device__ float g_blockmax[SIG_BLOCKS];

// ---------------------------------------------------------------------------
// Kernel 1: sigma[r] = ||delta[r, :]||_2 for r in [0, B*C).
// Warp-per-row, persistent grid (296 blocks), grid-stride over rows.
// Each lane loads 2 float4 (32 B) -> 1 KiB per warp per row, fully coalesced.
// Per-block max written to g_blockmax (plain store: replay-deterministic,
// no init kernel / no global atomics needed).
// ---------------------------------------------------------------------------
__global__ void __launch_bounds__(512)
pa_sigma_kernel(const float* __restrict__ delta)
{
    const int lane = threadIdx.x & 31;
    const int wid  = threadIdx.x >> 5;              // 0..15
    const int warps_per_block = 512 / 32;           // 16
    const int gwarp = blockIdx.x * warps_per_block + wid;
    const int warp_stride = SIG_BLOCKS * warps_per_block;   // 4736

    float lmax = 0.0f;

    #pragma unroll 2
    for (int row = gwarp; row < B_DIM * C_DIM; row += warp_stride) {
        const float4* p = reinterpret_cast<const float4*>(delta + (size_t)row * D_DIM);
        float4 a = p[lane];        // first 512 B of the row
        float4 b = p[lane + 32];   // second 512 B
        float s = a.x * a.x + a.y * a.y + a.z * a.z + a.w * a.w
                + b.x * b.x + b.y * b.y + b.z * b.z + b.w * b.w;

        #pragma unroll
        for (int o = 16; o > 0; o >>= 1)
            s += __shfl_xor_sync(0xffffffffu, s, o);

        float sig = sqrtf(s);                       // same value in all lanes
        if (lane == 0) g_sigma[row] = sig;
        lmax = fmaxf(lmax, sig);
    }

    // Block-level max -> g_blockmax[blockIdx.x]
    __shared__ float smax[16];
    if (lane == 0) smax[wid] = lmax;
    __syncthreads();
    if (wid == 0) {
        float v = (lane < warps_per_block) ? smax[lane] : 0.0f;
        #pragma unroll
        for (int o = 8; o > 0; o >>= 1)
            v = fmaxf(v, __shfl_xor_sync(0xffffffffu, v, o));
        if (lane == 0) g_blockmax[blockIdx.x] = v;
    }
}

// HW tanh (sm_75+): ~1e-6 rel error, plenty within the 1e-3 tolerance.
__device__ __forceinline__ float tanh_approx(float x) {
    float r;
    asm("tanh.approx.f32 %0, %1;" : "=f"(r) : "f"(x));
    return r;
}

// ---------------------------------------------------------------------------
// Kernel 2: per batch-row b (one block of C_DIM=512 threads):
//   gmax = max over g_blockmax
//   t    = tanh(1 - sigma / gmax)
//   att  = softmax_C(t)
//   zero the K_SEL smallest att values (ties -> lowest index), write out.
// Selection: 4-pass 8-bit radix select on float bit patterns (all positive),
// with warp-shuffle scans (4 __syncthreads per pass).
// ---------------------------------------------------------------------------
__global__ void __launch_bounds__(512)
pa_select_kernel(float* __restrict__ out)
{
    const int b = blockIdx.x;
    const int i = threadIdx.x;          // 0..511 == column index
    const int lane = i & 31;
    const int w    = i >> 5;            // warp id 0..15

    __shared__ float    s_red[16];
    __shared__ unsigned s_hist[256];
    __shared__ unsigned s_wsum[8];
    __shared__ unsigned s_bin, s_excl;
    __shared__ int      s_wcnt[16];

    // ---- global max from per-block maxima (L2-resident, broadcast reads) ----
    {
        float v = (i < SIG_BLOCKS) ? g_blockmax[i] : 0.0f;
        #pragma unroll
        for (int o = 16; o > 0; o >>= 1)
            v = fmaxf(v, __shfl_xor_sync(0xffffffffu, v, o));
        if (lane == 0) s_red[w] = v;
    }
    __syncthreads();
    float gmax = s_red[0];
    #pragma unroll
    for (int j = 1; j < 16; j++) gmax = fmaxf(gmax, s_red[j]);
    __syncthreads();                    // s_red is reused below

    const float sig = g_sigma[b * C_DIM + i];
    const float t   = tanh_approx(1.0f - sig / gmax);

    // ---- block max of t (softmax stabilization) ----
    float m = t;
    #pragma unroll
    for (int o = 16; o > 0; o >>= 1)
        m = fmaxf(m, __shfl_xor_sync(0xffffffffu, m, o));
    if (lane == 0) s_red[w] = m;
    __syncthreads();
    {
        float v = s_red[lane & 15];
        #pragma unroll
        for (int o = 8; o > 0; o >>= 1)
            v = fmaxf(v, __shfl_xor_sync(0xffffffffu, v, o));
        m = v;  // every thread computes the same block max via its own warp
    }
    __syncthreads();

    const float e = __expf(t - m);

    // ---- block sum of e ----
    float s = e;
    #pragma unroll
    for (int o = 16; o > 0; o >>= 1)
        s += __shfl_xor_sync(0xffffffffu, s, o);
    if (lane == 0) s_red[w] = s;
    __syncthreads();
    {
        float v = s_red[lane & 15];
        #pragma unroll
        for (int o = 8; o > 0; o >>= 1)
            v += __shfl_xor_sync(0xffffffffu, v, o);
        s = v;
    }

    const float att = e / s;
    const unsigned key = __float_as_uint(att);   // att > 0: bit order == value order

    // ---- radix select: find k-th smallest key (k = K_SEL) ----
    unsigned prefix = 0u;       // high bits of the k-th smallest, resolved so far
    unsigned krem   = K_SEL;    // 1-based rank remaining within current bucket

    #pragma unroll
    for (int shift = 24; shift >= 0; shift -= 8) {
        if (i < 256) s_hist[i] = 0u;
        __syncthreads();

        const bool in_bucket = (shift == 24) || ((key >> (shift + 8)) == prefix);
        if (in_bucket) atomicAdd(&s_hist[(key >> shift) & 255u], 1u);
        __syncthreads();

        // inclusive scan over 256 bins: warp shuffle scan + cross-warp offsets
        unsigned h = 0u, incl = 0u;
        if (i < 256) {
            h = s_hist[i];
            unsigned x = h;
            #pragma unroll
            for (int o = 1; o < 32; o <<= 1) {
                unsigned y = __shfl_up_sync(0xffffffffu, x, o);
                if (lane >= o) x += y;
            }
            if (lane == 31) s_wsum[w] = x;    // warp totals (warps 0..7)
            incl = x;
        }
        __syncthreads();
        if (i < 256) {
            unsigned off = 0u;
            #pragma unroll
            for (int j = 0; j < 8; j++)
                if (j < w) off += s_wsum[j];
            incl += off;
            unsigned excl = incl - h;
            // bin containing rank 'krem' (1-based)
            if (incl >= krem && excl < krem) { s_bin = (unsigned)i; s_excl = excl; }
        }
        __syncthreads();

        prefix = (prefix << 8) | s_bin;
        krem  -= s_excl;
        __syncthreads();   // protect s_bin/s_excl before next pass's writes
    }

    const unsigned T = prefix;          // exact bits of the k-th smallest att
    const unsigned tie_budget = krem;   // how many values == T get zeroed (lowest idx first)

    // ---- tie rank: index-ordered prefix count of (key == T) ----
    const bool eq = (key == T);
    const unsigned bal = __ballot_sync(0xffffffffu, eq);
    if (lane == 0) s_wcnt[w] = __popc(bal);
    __syncthreads();
    int woff = 0;
    #pragma unroll
    for (int j = 0; j < 16; j++)
        if (j < w) woff += s_wcnt[j];
    const unsigned tie_rank = (unsigned)woff + (unsigned)__popc(bal & ((1u << lane) - 1u));

    const bool zero = (key < T) || (eq && tie_rank < tie_budget);
    out[b * C_DIM + i] = zero ? 0.0f : att;
}

// ---------------------------------------------------------------------------
// Launch: two kernels, no init pass, graph-capturable, allocation-free.
// ---------------------------------------------------------------------------
extern "C" void kernel_launch(void* const* d_in, const int* in_sizes, int n_in,
                              void* d_out, int out_size)
{
    const float* delta = (const float*)d_in[0];
    float* out = (float*)d_out;
    (void)in_sizes; (void)n_in; (void)out_size;   // shapes fixed for this problem

    pa_sigma_kernel<<<SIG_BLOCKS, 512>>>(delta);
    pa_select_kernel<<<B_DIM, C_DIM>>>(out);
}

// round 5
// speedup vs baseline: 1.3147x; 1.3147x over previous
#include <cuda_runtime.h>
#include <math.h>

// Problem constants (PerturbationAttention): delta [B, C, D] fp32, k = 256
#define B_DIM 2048
#define C_DIM 512
#define D_DIM 256
#define K_SEL 256
#define SIG_BLOCKS 592   // 148 SMs * 4 resident blocks of 512 threads (full 64 warps/SM)

// Scratch (no allocations allowed): sigma buffer (4 MB) + per-block maxima.
__device__ float g_sigma[B_DIM * C_DIM];
__device__ float g_blockmax[SIG_BLOCKS];

// ---------------------------------------------------------------------------
// Kernel 1: sigma[r] = ||delta[r, :]||_2 for r in [0, B*C).
// Warp-per-row, grid-stride over rows. 592 blocks -> 4 blocks/SM resident
// (64 warps/SM) so the per-iteration shuffle-reduce chain is hidden by
// other warps. Each lane loads 2 float4 (32 B) -> 1 KiB per warp per row.
// Per-block max written to g_blockmax (plain store: replay-deterministic).
// ---------------------------------------------------------------------------
__global__ void __launch_bounds__(512, 4)
pa_sigma_kernel(const float* __restrict__ delta)
{
    const int lane = threadIdx.x & 31;
    const int wid  = threadIdx.x >> 5;              // 0..15
    const int warps_per_block = 512 / 32;           // 16
    const int gwarp = blockIdx.x * warps_per_block + wid;
    const int warp_stride = SIG_BLOCKS * warps_per_block;   // 9472

    float lmax = 0.0f;

    #pragma unroll 2
    for (int row = gwarp; row < B_DIM * C_DIM; row += warp_stride) {
        const float4* p = reinterpret_cast<const float4*>(delta + (size_t)row * D_DIM);
        float4 a = p[lane];        // first 512 B of the row
        float4 b = p[lane + 32];   // second 512 B
        float s = a.x * a.x + a.y * a.y + a.z * a.z + a.w * a.w
                + b.x * b.x + b.y * b.y + b.z * b.z + b.w * b.w;

        #pragma unroll
        for (int o = 16; o > 0; o >>= 1)
            s += __shfl_xor_sync(0xffffffffu, s, o);

        float sig = sqrtf(s);                       // same value in all lanes
        if (lane == 0) g_sigma[row] = sig;
        lmax = fmaxf(lmax, sig);
    }

    // Block-level max -> g_blockmax[blockIdx.x]
    __shared__ float smax[16];
    if (lane == 0) smax[wid] = lmax;
    __syncthreads();
    if (wid == 0) {
        float v = (lane < warps_per_block) ? smax[lane] : 0.0f;
        #pragma unroll
        for (int o = 8; o > 0; o >>= 1)
            v = fmaxf(v, __shfl_xor_sync(0xffffffffu, v, o));
        if (lane == 0) g_blockmax[blockIdx.x] = v;
    }
}

// HW tanh (sm_75+): ~1e-6 rel error, plenty within the 1e-3 tolerance.
__device__ __forceinline__ float tanh_approx(float x) {
    float r;
    asm("tanh.approx.f32 %0, %1;" : "=f"(r) : "f"(x));
    return r;
}

// ---------------------------------------------------------------------------
// Kernel 2: per batch-row b (one block of C_DIM=512 threads):
//   gmax = max over g_blockmax
//   t    = tanh(1 - sigma / gmax)
//   att  = softmax_C(t)
//   zero the K_SEL smallest att values (ties -> lowest index), write out.
// Selection: 4-pass 8-bit radix select on float bit patterns (all positive).
// Histogram uses warp-aggregated atomics (__match_any_sync): clustered digits
// cost 1 atomic per warp instead of 32 serialized same-address ATOMS.
// ---------------------------------------------------------------------------
__global__ void __launch_bounds__(512)
pa_select_kernel(float* __restrict__ out)
{
    const int b = blockIdx.x;
    const int i = threadIdx.x;          // 0..511 == column index
    const int lane = i & 31;
    const int w    = i >> 5;            // warp id 0..15

    __shared__ float    s_red[16];
    __shared__ unsigned s_hist[256];
    __shared__ unsigned s_wsum[8];
    __shared__ unsigned s_bin, s_excl;
    __shared__ int      s_wcnt[16];

    // ---- global max from per-block maxima (L2-resident) ----
    {
        float v = (i < SIG_BLOCKS) ? g_blockmax[i] : 0.0f;
        if (i + 512 < SIG_BLOCKS) v = fmaxf(v, g_blockmax[i + 512]);
        #pragma unroll
        for (int o = 16; o > 0; o >>= 1)
            v = fmaxf(v, __shfl_xor_sync(0xffffffffu, v, o));
        if (lane == 0) s_red[w] = v;
    }
    __syncthreads();
    float gmax = s_red[0];
    #pragma unroll
    for (int j = 1; j < 16; j++) gmax = fmaxf(gmax, s_red[j]);
    __syncthreads();                    // s_red is reused below

    const float sig = g_sigma[b * C_DIM + i];
    const float t   = tanh_approx(1.0f - sig / gmax);

    // ---- block max of t (softmax stabilization) ----
    float m = t;
    #pragma unroll
    for (int o = 16; o > 0; o >>= 1)
        m = fmaxf(m, __shfl_xor_sync(0xffffffffu, m, o));
    if (lane == 0) s_red[w] = m;
    __syncthreads();
    {
        float v = s_red[lane & 15];
        #pragma unroll
        for (int o = 8; o > 0; o >>= 1)
            v = fmaxf(v, __shfl_xor_sync(0xffffffffu, v, o));
        m = v;  // every thread computes the same block max via its own warp
    }
    __syncthreads();

    const float e = __expf(t - m);

    // ---- block sum of e ----
    float s = e;
    #pragma unroll
    for (int o = 16; o > 0; o >>= 1)
        s += __shfl_xor_sync(0xffffffffu, s, o);
    if (lane == 0) s_red[w] = s;
    __syncthreads();
    {
        float v = s_red[lane & 15];
        #pragma unroll
        for (int o = 8; o > 0; o >>= 1)
            v += __shfl_xor_sync(0xffffffffu, v, o);
        s = v;
    }

    const float att = e / s;
    const unsigned key = __float_as_uint(att);   // att > 0: bit order == value order

    // ---- radix select: find k-th smallest key (k = K_SEL) ----
    unsigned prefix = 0u;       // high bits of the k-th smallest, resolved so far
    unsigned krem   = K_SEL;    // 1-based rank remaining within current bucket

    #pragma unroll
    for (int shift = 24; shift >= 0; shift -= 8) {
        if (i < 256) s_hist[i] = 0u;
        __syncthreads();

        const bool in_bucket = (shift == 24) || ((key >> (shift + 8)) == prefix);
        // Warp-aggregated histogram: lanes with equal digit elect one leader
        // who adds the group count once. Sentinel 256 for non-bucket lanes.
        {
            unsigned digit = in_bucket ? ((key >> shift) & 255u) : 256u;
            unsigned grp   = __match_any_sync(0xffffffffu, digit);
            unsigned leader = __ffs(grp) - 1u;
            if (in_bucket && lane == leader)
                atomicAdd(&s_hist[digit], (unsigned)__popc(grp));
        }
        __syncthreads();

        // inclusive scan over 256 bins: warp shuffle scan + cross-warp offsets
        unsigned h = 0u, incl = 0u;
        if (i < 256) {
            h = s_hist[i];
            unsigned x = h;
            #pragma unroll
            for (int o = 1; o < 32; o <<= 1) {
                unsigned y = __shfl_up_sync(0xffffffffu, x, o);
                if (lane >= o) x += y;
            }
            if (lane == 31) s_wsum[w] = x;    // warp totals (warps 0..7)
            incl = x;
        }
        __syncthreads();
        if (i < 256) {
            unsigned off = 0u;
            #pragma unroll
            for (int j = 0; j < 8; j++)
                if (j < w) off += s_wsum[j];
            incl += off;
            unsigned excl = incl - h;
            // bin containing rank 'krem' (1-based)
            if (incl >= krem && excl < krem) { s_bin = (unsigned)i; s_excl = excl; }
        }
        __syncthreads();

        prefix = (prefix << 8) | s_bin;
        krem  -= s_excl;
        __syncthreads();   // protect s_bin/s_excl before next pass's writes
    }

    const unsigned T = prefix;          // exact bits of the k-th smallest att
    const unsigned tie_budget = krem;   // how many values == T get zeroed (lowest idx first)

    // ---- tie rank: index-ordered prefix count of (key == T) ----
    const bool eq = (key == T);
    const unsigned bal = __ballot_sync(0xffffffffu, eq);
    if (lane == 0) s_wcnt[w] = __popc(bal);
    __syncthreads();
    int woff = 0;
    #pragma unroll
    for (int j = 0; j < 16; j++)
        if (j < w) woff += s_wcnt[j];
    const unsigned tie_rank = (unsigned)woff + (unsigned)__popc(bal & ((1u << lane) - 1u));

    const bool zero = (key < T) || (eq && tie_rank < tie_budget);
    out[b * C_DIM + i] = zero ? 0.0f : att;
}

// ---------------------------------------------------------------------------
// Launch: two kernels, no init pass, graph-capturable, allocation-free.
// ---------------------------------------------------------------------------
extern "C" void kernel_launch(void* const* d_in, const int* in_sizes, int n_in,
                              void* d_out, int out_size)
{
    const float* delta = (const float*)d_in[0];
    float* out = (float*)d_out;
    (void)in_sizes; (void)n_in; (void)out_size;   // shapes fixed for this problem

    pa_sigma_kernel<<<SIG_BLOCKS, 512>>>(delta);
    pa_select_kernel<<<B_DIM, C_DIM>>>(out);
}